// round 10
// baseline (speedup 1.0000x reference)
#include <cuda_runtime.h>
#include <cstdint>

#define Bn 16
#define Cn 19
#define Hn 512
#define Wn 512
#define HWn (Hn * Wn)          // 262144
#define NPIX (Bn * HWn)        // 4194304
#define W4 (Wn / 4)            // 128
#define HW4 (HWn / 4)          // 65536
#define TPB 256
#define NBLK (NPIX / 4 / TPB)  // 4096

__device__ double g_acc;       // zero at load; reset by last block each call
__device__ unsigned g_done;    // zero at load; reset by last block each call

// streaming 128-bit load: L2-only, no L1 allocation
__device__ __forceinline__ void ldcg4(const float4* p, float& x, float& y,
                                      float& z, float& w) {
    asm volatile("ld.global.cg.v4.f32 {%0,%1,%2,%3}, [%4];"
                 : "=f"(x), "=f"(y), "=f"(z), "=f"(w) : "l"(p));
}

// fold one channel's float4 into the 4 per-pixel partial sums + xt selects
#define FOLD(C, FX, FY, FZ, FW)                                   \
    do {                                                          \
        s[0] += __expf(FX); if ((C) == c0_0) xt0 = (FX);          \
        s[1] += __expf(FY); if ((C) == c0_1) xt1 = (FY);          \
        s[2] += __expf(FZ); if ((C) == c0_2) xt2 = (FZ);          \
        s[3] += __expf(FW); if ((C) == c0_3) xt3 = (FW);          \
    } while (0)

// STRIDE compile-time: 2 = int64 targets (read low word), 1 = int32.
template <int STRIDE>
__device__ __forceinline__ float quad_loss(const float* __restrict__ pred,
                                           const int* __restrict__ tg,
                                           int b, int h, int w4) {
    const int w0 = w4 << 2;
    const int* tr = tg + (size_t)(b * HWn + h * Wn + w0) * STRIDE;  // row h, col w0

    // center targets
    const int c0_0 = __ldg(tr);
    const int c0_1 = __ldg(tr + STRIDE);
    const int c0_2 = __ldg(tr + 2 * STRIDE);
    const int c0_3 = __ldg(tr + 3 * STRIDE);

    // ---- edge masks for the 4-px strip
    int d0 = 0, d1 = 0, d2 = 0, d3 = 0;
    if (h > 0 && h < Hn - 1 && w4 > 0 && w4 < W4 - 1) {
        // interior: rows h-1,h,h+1 x cols w0-1..w0+4, one row live at a time
#pragma unroll
        for (int ro = -1; ro <= 1; ro++) {
            int n0 = __ldg(tr + (ro * Wn - 1) * STRIDE);
            int n1 = __ldg(tr + (ro * Wn + 0) * STRIDE);
            int n2 = __ldg(tr + (ro * Wn + 1) * STRIDE);
            int n3 = __ldg(tr + (ro * Wn + 2) * STRIDE);
            int n4 = __ldg(tr + (ro * Wn + 3) * STRIDE);
            int n5 = __ldg(tr + (ro * Wn + 4) * STRIDE);
            if (ro == 0) {   // skip center element per pixel
                d0 |= (n0 ^ c0_0) | (n2 ^ c0_0);
                d1 |= (n1 ^ c0_1) | (n3 ^ c0_1);
                d2 |= (n2 ^ c0_2) | (n4 ^ c0_2);
                d3 |= (n3 ^ c0_3) | (n5 ^ c0_3);
            } else {
                d0 |= (n0 ^ c0_0) | (n1 ^ c0_0) | (n2 ^ c0_0);
                d1 |= (n1 ^ c0_1) | (n2 ^ c0_1) | (n3 ^ c0_1);
                d2 |= (n2 ^ c0_2) | (n3 ^ c0_2) | (n4 ^ c0_2);
                d3 |= (n3 ^ c0_3) | (n4 ^ c0_3) | (n5 ^ c0_3);
            }
        }
    } else {
        // border quads (~3%): guarded per-pixel path
        int dd[4] = {0, 0, 0, 0};
        const int cc[4] = {c0_0, c0_1, c0_2, c0_3};
#pragma unroll
        for (int i = 0; i < 4; i++) {
            int w = w0 + i;
#pragma unroll
            for (int dy = -1; dy <= 1; dy++)
#pragma unroll
                for (int dx = -1; dx <= 1; dx++) {
                    if (dy == 0 && dx == 0) continue;
                    int hh = h + dy, ww = w + dx;
                    if (hh >= 0 && hh < Hn && ww >= 0 && ww < Wn)
                        dd[i] |= (__ldg(tr + (dy * Wn + (i + dx)) * STRIDE) ^ cc[i]);
                }
        }
        d0 = dd[0]; d1 = dd[1]; d2 = dd[2]; d3 = dd[3];
    }

    // ---- predictions: 19 x LDG.128 streaming, grouped 5/5/5/4 to bound regs
    const float4* p4 = (const float4*)pred + (size_t)b * Cn * HW4 + h * W4 + w4;
    float s[4] = {0.f, 0.f, 0.f, 0.f};
    float xt0 = 0.f, xt1 = 0.f, xt2 = 0.f, xt3 = 0.f;

#pragma unroll
    for (int g = 0; g < 4; g++) {
        const int base = g * 5;
        const int cnt = (g == 3) ? 4 : 5;
        float x[5], y[5], z[5], w[5];
#pragma unroll
        for (int k = 0; k < cnt; k++)
            ldcg4(p4 + (size_t)(base + k) * HW4, x[k], y[k], z[k], w[k]);
#pragma unroll
        for (int k = 0; k < cnt; k++)
            FOLD(base + k, x[k], y[k], z[k], w[k]);
    }

    float ce0 = __logf(s[0]) - xt0;
    float ce1 = __logf(s[1]) - xt1;
    float ce2 = __logf(s[2]) - xt2;
    float ce3 = __logf(s[3]) - xt3;
    float v = (d0 ? 2.f : 1.f) * ce0 + (d1 ? 2.f : 1.f) * ce1;
    v += (d2 ? 2.f : 1.f) * ce2 + (d3 ? 2.f : 1.f) * ce3;
    return v;
}

__global__ void __launch_bounds__(TPB)
edgeloss_fused(const float* __restrict__ pred,
               const unsigned int* __restrict__ tg_raw,
               float* __restrict__ out) {
    const unsigned FULL = 0xFFFFFFFFu;
    __shared__ int s_is64;
    __shared__ float s_warp[8];

    // dtype detect: warp 0 checks 64 word-pairs; int32 false-positive p=(1/19)^64
    if (threadIdx.x < 32) {
        int lane = threadIdx.x;
        bool ok = true;
#pragma unroll
        for (int k = 0; k < 2; k++) {
            int i = lane + 32 * k;
            ok &= (__ldg(&tg_raw[2 * i + 1]) == 0u) && (__ldg(&tg_raw[2 * i]) < 19u);
        }
        int all_ok = __all_sync(FULL, ok);
        if (lane == 0) s_is64 = all_ok;
    }
    __syncthreads();

    const int q  = blockIdx.x * TPB + threadIdx.x;   // quad index
    const int b  = q >> 16;               // / HW4
    const int r  = q & (HW4 - 1);
    const int h  = r >> 7;                // / W4
    const int w4 = r & (W4 - 1);
    const int* tg = (const int*)tg_raw;

    float val;
    if (s_is64) val = quad_loss<2>(pred, tg, b, h, w4);
    else        val = quad_loss<1>(pred, tg, b, h, w4);

    // block reduce
#pragma unroll
    for (int off = 16; off > 0; off >>= 1)
        val += __shfl_down_sync(FULL, val, off);
    int lane = threadIdx.x & 31;
    int wid = threadIdx.x >> 5;
    if (lane == 0) s_warp[wid] = val;
    __syncthreads();
    if (wid == 0) {
        float bs = (lane < 8) ? s_warp[lane] : 0.0f;
#pragma unroll
        for (int off = 4; off > 0; off >>= 1)
            bs += __shfl_down_sync(FULL, bs, off);
        if (lane == 0) {
            // FENCE-FREE ordering (no CCTL.IVALL L1 flush): atomics perform at
            // L2; register data-dependence orders g_acc-add before g_done-inc.
            double old = atomicAdd(&g_acc, (double)bs);
            unsigned dep = (unsigned)__double2loint(old);
            asm volatile("and.b32 %0, %0, 0;" : "+r"(dep));  // opaque zero
            unsigned done = atomicAdd(&g_done, 1u + dep);
            if (done == NBLK - 1) {
                double total = atomicAdd(&g_acc, 0.0);
                out[0] = (float)(total / (double)NPIX);
                g_acc = 0.0;               // reset for next graph replay
                g_done = 0u;
            }
        }
    }
}

extern "C" void kernel_launch(void* const* d_in, const int* in_sizes, int n_in,
                              void* d_out, int out_size) {
    const float* pred = (const float*)d_in[0];
    const unsigned int* targ = (const unsigned int*)d_in[1];
    float* out = (float*)d_out;
    edgeloss_fused<<<NBLK, TPB>>>(pred, targ, out);
}